// round 14
// baseline (speedup 1.0000x reference)
#include <cuda_runtime.h>
#include <cuda_bf16.h>
#include <cstdint>

// Problem constants
static constexpr int BB  = 8192;   // batch
static constexpr int DK  = 1024;   // embedding dim
static constexpr int NT  = 64;     // 8192 / 128 tiles per side
static constexpr int NCH = 8;      // 1024 / 128 K-chunks (int8: BK=128)
static constexpr float HNW_SCALE = 1.5f;   // 1 + hard_negative_weight

static constexpr int STAGE_BYTES = 32768;            // A(16K) + B(16K) int8
static constexpr int SMEM_BYTES  = 3 * STAGE_BYTES;  // 98304; 2 CTAs/SM

static constexpr int QBLK = 592;   // quant: 4 CTAs/SM, grid-stride 3-4 rows/warp
static constexpr int QWARPS = QBLK * 8;

// ------------------------- device scratch (static, no allocs) -------------------------
__device__ __align__(256) int8_t g_Iq[(size_t)BB * DK];
__device__ __align__(256) int8_t g_Sq[(size_t)BB * DK];
__device__ float g_qsI[BB];        // rowmax/127
__device__ float g_qsS[BB];        // rowmax/127 * 20  (1/T folded here)
// partials laid out TRANSPOSED: [idx * NT + tile] -> combine reads 64 consecutive floats
__device__ __align__(256) float g_rowMax[BB * NT];
__device__ __align__(256) float g_rowSum[BB * NT];
__device__ __align__(256) float g_rowHn [BB * NT];
__device__ __align__(256) float g_colMax[BB * NT];
__device__ __align__(256) float g_colSum[BB * NT];
__device__ __align__(256) float g_colHn [BB * NT];
__device__ float g_diag  [BB];
__device__ float g_part  [64];
__device__ unsigned g_ctr = 0;

// ------------------------- helpers -------------------------
static __device__ __forceinline__ uint32_t smem_u32(const void* p) {
    uint32_t a;
    asm("{ .reg .u64 t; cvta.to.shared.u64 t, %1; cvt.u32.u64 %0, t; }" : "=r"(a) : "l"(p));
    return a;
}
static __device__ __forceinline__ void cp16(uint32_t s, const void* g) {
    asm volatile("cp.async.cg.shared.global [%0], [%1], 16;" :: "r"(s), "l"(g) : "memory");
}
// Swizzled smem addr for a [128 rows][128 B] tile; 16B chunks xor'd by row&7
static __device__ __forceinline__ uint32_t sw_addr(uint32_t base, int row, int kchunk) {
    return base + (uint32_t)(row * 128) + (uint32_t)(((kchunk ^ (row & 7)) << 4));
}
static __device__ __forceinline__ void ldsm_x4(uint32_t& r0, uint32_t& r1, uint32_t& r2,
                                               uint32_t& r3, uint32_t addr) {
    asm volatile("ldmatrix.sync.aligned.m8n8.x4.shared.b16 {%0,%1,%2,%3}, [%4];"
                 : "=r"(r0), "=r"(r1), "=r"(r2), "=r"(r3) : "r"(addr));
}
static __device__ __forceinline__ void imma16832(int& c0, int& c1, int& c2, int& c3,
                                                 uint32_t a0, uint32_t a1, uint32_t a2,
                                                 uint32_t a3, uint32_t b0, uint32_t b1) {
    asm volatile(
        "mma.sync.aligned.m16n8k32.row.col.s32.s8.s8.s32 "
        "{%0,%1,%2,%3}, {%4,%5,%6,%7}, {%8,%9}, {%0,%1,%2,%3};"
        : "+r"(c0), "+r"(c1), "+r"(c2), "+r"(c3)
        : "r"(a0), "r"(a1), "r"(a2), "r"(a3), "r"(b0), "r"(b1));
}

// ------------------------- kernel 1: fp32 -> int8 quant (persistent warps) ---------------
__global__ void __launch_bounds__(256) quant_kernel(const float* __restrict__ I,
                                                    const float* __restrict__ S) {
    const int gwarp = (blockIdx.x * 256 + threadIdx.x) >> 5;
    const int lane = threadIdx.x & 31;

    for (int w = gwarp; w < 2 * BB; w += QWARPS) {
        const bool isI = w < BB;
        const int r = isI ? w : w - BB;
        const float4* src = (const float4*)((isI ? I : S) + (size_t)r * DK);

        float4 v[8];
        float m = 0.f;
#pragma unroll
        for (int i = 0; i < 8; i++) {
            v[i] = src[lane + 32 * i];
            m = fmaxf(m, fmaxf(fmaxf(fabsf(v[i].x), fabsf(v[i].y)),
                               fmaxf(fabsf(v[i].z), fabsf(v[i].w))));
        }
#pragma unroll
        for (int o = 16; o; o >>= 1) m = fmaxf(m, __shfl_xor_sync(~0u, m, o));
        m = fmaxf(m, 1e-20f);
        const float inv = 127.0f / m;

        char4* dst = (char4*)((isI ? g_Iq : g_Sq) + (size_t)r * DK);
#pragma unroll
        for (int i = 0; i < 8; i++) {
            char4 q;
            q.x = (char)__float2int_rn(v[i].x * inv);
            q.y = (char)__float2int_rn(v[i].y * inv);
            q.z = (char)__float2int_rn(v[i].z * inv);
            q.w = (char)__float2int_rn(v[i].w * inv);
            dst[lane + 32 * i] = q;
        }
        if (lane == 0) {
            if (isI) g_qsI[r] = m / 127.0f;
            else     g_qsS[r] = (m / 127.0f) * 20.0f;
        }
    }
}

// ------------------------- kernel 2: int8 GEMM tile + register epilogue ------------------
static __device__ __forceinline__ void load_chunk(int tid, const int8_t* Ap,
                                                  const int8_t* Bp,
                                                  uint32_t DATA, int kc) {
    int s = kc % 3;
    uint32_t abase = DATA + (uint32_t)s * STAGE_BYTES;
    uint32_t bbase = abase + 16384u;
    const int8_t* ga0 = Ap + kc * 128;
    const int8_t* gb0 = Bp + kc * 128;
#pragma unroll
    for (int i = 0; i < 4; i++) {
        int v = tid + i * 256;
        int row = v >> 3, cv = v & 7;
        cp16(sw_addr(abase, row, cv), ga0 + (size_t)row * DK + cv * 16);
        cp16(sw_addr(bbase, row, cv), gb0 + (size_t)row * DK + cv * 16);
    }
}

__global__ void __launch_bounds__(256, 2) gemm_kernel() {
    extern __shared__ char smem[];
    const uint32_t DATA = smem_u32(smem);
    const int tid = threadIdx.x, wid = tid >> 5, lane = tid & 31;
    const int wm = wid >> 1, wn = wid & 1;   // 4 x 2 warp grid
    const int bx = blockIdx.x, by = blockIdx.y;

    const int8_t* Ap = g_Iq + (size_t)by * 128 * DK;
    const int8_t* Bp = g_Sq + (size_t)bx * 128 * DK;

    int acc[2][8][4];
#pragma unroll
    for (int mt = 0; mt < 2; mt++)
#pragma unroll
        for (int nt = 0; nt < 8; nt++)
#pragma unroll
            for (int q = 0; q < 4; q++) acc[mt][nt][q] = 0;

    load_chunk(tid, Ap, Bp, DATA, 0);
    asm volatile("cp.async.commit_group;" ::: "memory");
    load_chunk(tid, Ap, Bp, DATA, 1);
    asm volatile("cp.async.commit_group;" ::: "memory");

    // ONE barrier per chunk: prefetch k+2 targets the slot consumed in iter k-1.
    for (int k = 0; k < NCH; k++) {
        asm volatile("cp.async.wait_group 1;" ::: "memory");   // stage k arrived
        __syncthreads();
        if (k + 2 < NCH) load_chunk(tid, Ap, Bp, DATA, k + 2);
        asm volatile("cp.async.commit_group;" ::: "memory");   // uniform accounting
        int s = k % 3;
        uint32_t abase = DATA + (uint32_t)s * STAGE_BYTES;
        uint32_t bbase = abase + 16384u;
#pragma unroll
        for (int kk = 0; kk < 4; kk++) {   // 4 x K=32 per 128B chunk-row
            uint32_t a[2][4];
#pragma unroll
            for (int mt = 0; mt < 2; mt++) {
                int row = wm * 32 + mt * 16 + (lane & 15);
                int kch = 2 * kk + (lane >> 4);
                ldsm_x4(a[mt][0], a[mt][1], a[mt][2], a[mt][3], sw_addr(abase, row, kch));
            }
            uint32_t b[8][2];
#pragma unroll
            for (int np = 0; np < 4; np++) {
                int nrow = wn * 64 + np * 16 + (lane & 7) + ((lane >> 4) << 3);
                int kch = 2 * kk + ((lane >> 3) & 1);
                uint32_t r0, r1, r2, r3;
                ldsm_x4(r0, r1, r2, r3, sw_addr(bbase, nrow, kch));
                b[2 * np][0] = r0; b[2 * np][1] = r1;
                b[2 * np + 1][0] = r2; b[2 * np + 1][1] = r3;
            }
#pragma unroll
            for (int mt = 0; mt < 2; mt++)
#pragma unroll
                for (int nt = 0; nt < 8; nt++)
                    imma16832(acc[mt][nt][0], acc[mt][nt][1], acc[mt][nt][2], acc[mt][nt][3],
                              a[mt][0], a[mt][1], a[mt][2], a[mt][3], b[nt][0], b[nt][1]);
        }
    }
    asm volatile("cp.async.wait_group 0;" ::: "memory");
    __syncthreads();   // pipeline smem free -> reuse for tiny epilogue partials

    // ---------------- register epilogue ----------------
    const int rbase = wm * 32 + (lane >> 2);
    const int cbase = wn * 64 + 2 * (lane & 3);
    const bool dT = (bx == by);

    float x[2][8][4];
    {
        float sI[2][2], sS[8][2];
#pragma unroll
        for (int mt = 0; mt < 2; mt++) {
            sI[mt][0] = g_qsI[by * 128 + rbase + mt * 16];
            sI[mt][1] = g_qsI[by * 128 + rbase + mt * 16 + 8];
        }
#pragma unroll
        for (int nt = 0; nt < 8; nt++) {
            sS[nt][0] = g_qsS[bx * 128 + cbase + nt * 8];
            sS[nt][1] = g_qsS[bx * 128 + cbase + nt * 8 + 1];
        }
#pragma unroll
        for (int mt = 0; mt < 2; mt++)
#pragma unroll
            for (int nt = 0; nt < 8; nt++)
#pragma unroll
                for (int qr = 0; qr < 2; qr++)
#pragma unroll
                    for (int qc = 0; qc < 2; qc++)
                        x[mt][nt][qr * 2 + qc] =
                            (float)acc[mt][nt][qr * 2 + qc] * (sI[mt][qr] * sS[nt][qc]);
    }

    float* sm = (float*)smem;
    float* rm = sm;          // [2][128]
    float* rh = sm + 256;    // [2][128]
    float* rs = sm + 512;    // [2][128]
    float* cm = sm + 768;    // [4][128]
    float* ch = sm + 1280;   // [4][128]
    float* cs = sm + 1792;   // [4][128]

    // pass A: maxes (+diag capture)
#pragma unroll
    for (int g = 0; g < 4; g++) {
        int mt = g >> 1, qr = g & 1;
        int r_loc = rbase + mt * 16 + qr * 8;
        float m = -3.4e38f, h = -3.4e38f;
#pragma unroll
        for (int nt = 0; nt < 8; nt++) {
#pragma unroll
            for (int qc = 0; qc < 2; qc++) {
                float v = x[mt][nt][qr * 2 + qc];
                m = fmaxf(m, v);
                int c_loc = cbase + nt * 8 + qc;
                if (dT && c_loc == r_loc) g_diag[by * 128 + r_loc] = v;
                else h = fmaxf(h, v);
            }
        }
        m = fmaxf(m, __shfl_xor_sync(~0u, m, 1));
        m = fmaxf(m, __shfl_xor_sync(~0u, m, 2));
        h = fmaxf(h, __shfl_xor_sync(~0u, h, 1));
        h = fmaxf(h, __shfl_xor_sync(~0u, h, 2));
        if ((lane & 3) == 0) { rm[wn * 128 + r_loc] = m; rh[wn * 128 + r_loc] = h; }
    }
#pragma unroll
    for (int nt = 0; nt < 8; nt++) {
#pragma unroll
        for (int qc = 0; qc < 2; qc++) {
            int c_loc = cbase + nt * 8 + qc;
            float m = -3.4e38f, h = -3.4e38f;
#pragma unroll
            for (int g = 0; g < 4; g++) {
                int mt = g >> 1, qr = g & 1;
                float v = x[mt][nt][qr * 2 + qc];
                m = fmaxf(m, v);
                int r_loc = rbase + mt * 16 + qr * 8;
                if (!(dT && c_loc == r_loc)) h = fmaxf(h, v);
            }
            m = fmaxf(m, __shfl_xor_sync(~0u, m, 4));
            m = fmaxf(m, __shfl_xor_sync(~0u, m, 8));
            m = fmaxf(m, __shfl_xor_sync(~0u, m, 16));
            h = fmaxf(h, __shfl_xor_sync(~0u, h, 4));
            h = fmaxf(h, __shfl_xor_sync(~0u, h, 8));
            h = fmaxf(h, __shfl_xor_sync(~0u, h, 16));
            if ((lane >> 2) == 0) { cm[wm * 128 + c_loc] = m; ch[wm * 128 + c_loc] = h; }
        }
    }
    __syncthreads();

    // pass B: exp sums against the COMBINED maxes (partials then add exactly)
#pragma unroll
    for (int g = 0; g < 4; g++) {
        int mt = g >> 1, qr = g & 1;
        int r_loc = rbase + mt * 16 + qr * 8;
        float mrow = fmaxf(rm[r_loc], rm[128 + r_loc]);
        float s = 0.f;
#pragma unroll
        for (int nt = 0; nt < 8; nt++) {
            s += __expf(x[mt][nt][qr * 2] - mrow);
            s += __expf(x[mt][nt][qr * 2 + 1] - mrow);
        }
        s += __shfl_xor_sync(~0u, s, 1);
        s += __shfl_xor_sync(~0u, s, 2);
        if ((lane & 3) == 0) rs[wn * 128 + r_loc] = s;
    }
#pragma unroll
    for (int nt = 0; nt < 8; nt++) {
#pragma unroll
        for (int qc = 0; qc < 2; qc++) {
            int c_loc = cbase + nt * 8 + qc;
            float mcol = fmaxf(fmaxf(cm[c_loc], cm[128 + c_loc]),
                               fmaxf(cm[256 + c_loc], cm[384 + c_loc]));
            float s = 0.f;
#pragma unroll
            for (int g = 0; g < 4; g++) {
                int mt = g >> 1, qr = g & 1;
                s += __expf(x[mt][nt][qr * 2 + qc] - mcol);
            }
            s += __shfl_xor_sync(~0u, s, 4);
            s += __shfl_xor_sync(~0u, s, 8);
            s += __shfl_xor_sync(~0u, s, 16);
            if ((lane >> 2) == 0) cs[wm * 128 + c_loc] = s;
        }
    }
    __syncthreads();

    // final writes (TRANSPOSED layout: [idx * NT + tile])
    if (tid < 128) {
        int r = tid;
        float m = fmaxf(rm[r], rm[128 + r]);
        float h = fmaxf(rh[r], rh[128 + r]);
        float s = rs[r] + rs[128 + r];
        size_t o = (size_t)(by * 128 + r) * NT + bx;
        g_rowMax[o] = m;
        g_rowSum[o] = s;
        g_rowHn [o] = h;
    } else {
        int c = tid - 128;
        float m = fmaxf(fmaxf(cm[c], cm[128 + c]), fmaxf(cm[256 + c], cm[384 + c]));
        float h = fmaxf(fmaxf(ch[c], ch[128 + c]), fmaxf(ch[256 + c], ch[384 + c]));
        float s = cs[c] + cs[128 + c] + cs[256 + c] + cs[384 + c];
        size_t o = (size_t)(bx * 128 + c) * NT + by;
        g_colMax[o] = m;
        g_colSum[o] = s;
        g_colHn [o] = h;
    }
}

// ------------------------- kernel 3: merge partials -> loss; last block finalizes --------
__global__ void combine_kernel(float* __restrict__ out) {
    int i = blockIdx.x * blockDim.x + threadIdx.x;  // 0 .. 2*BB-1
    int idx = i & (BB - 1);
    const float *PM, *PS, *PH;
    if (i < BB) { PM = g_rowMax; PS = g_rowSum; PH = g_rowHn; }
    else        { PM = g_colMax; PS = g_colSum; PH = g_colHn; }

    // transposed layout: 64 consecutive floats per index -> float4 sweeps
    const float4* pm4 = (const float4*)(PM + (size_t)idx * NT);
    const float4* ps4 = (const float4*)(PS + (size_t)idx * NT);
    const float4* ph4 = (const float4*)(PH + (size_t)idx * NT);

    float m = -3.4e38f, h = -3.4e38f;
#pragma unroll
    for (int t = 0; t < NT / 4; t++) {
        float4 vm = pm4[t], vh = ph4[t];
        m = fmaxf(m, fmaxf(fmaxf(vm.x, vm.y), fmaxf(vm.z, vm.w)));
        h = fmaxf(h, fmaxf(fmaxf(vh.x, vh.y), fmaxf(vh.z, vh.w)));
    }
    float s = 0.f;
#pragma unroll
    for (int t = 0; t < NT / 4; t++) {
        float4 vm = pm4[t], vs = ps4[t];
        s += vs.x * __expf(vm.x - m);
        s += vs.y * __expf(vm.y - m);
        s += vs.z * __expf(vm.z - m);
        s += vs.w * __expf(vm.w - m);
    }

    float d = g_diag[idx];
    float loss;
    if (h > 0.f) {
        float M = fmaxf(m, HNW_SCALE * h);
        float S = s * __expf(m - M) - __expf(h - M) + __expf(HNW_SCALE * h - M);
        loss = M + __logf(S) - d;
    } else {
        float dd = HNW_SCALE * d;
        float snd = s - __expf(d - m);
        float M = fmaxf(h, dd);
        float S = snd * __expf(m - M) + __expf(dd - M);
        loss = M + __logf(S) - dd;
    }

    __shared__ float red[256];
    __shared__ bool last;
    red[threadIdx.x] = loss;
    __syncthreads();
    for (int o = 128; o > 0; o >>= 1) {
        if (threadIdx.x < (unsigned)o) red[threadIdx.x] += red[threadIdx.x + o];
        __syncthreads();
    }
    if (threadIdx.x == 0) {
        g_part[blockIdx.x] = red[0];
        __threadfence();
        last = (atomicAdd(&g_ctr, 1u) == 63u);
    }
    __syncthreads();
    if (last && threadIdx.x == 0) {
        float t = 0.f;
#pragma unroll
        for (int b = 0; b < 64; b++) t += g_part[b];
        out[0] = t / (float)(2 * BB);
        g_ctr = 0;  // reset for next graph replay
    }
}

// ------------------------- launch -------------------------
extern "C" void kernel_launch(void* const* d_in, const int* in_sizes, int n_in,
                              void* d_out, int out_size) {
    const float* I = (const float*)d_in[0];
    const float* S = (const float*)d_in[1];
    float* out = (float*)d_out;

    cudaFuncSetAttribute(gemm_kernel, cudaFuncAttributeMaxDynamicSharedMemorySize, SMEM_BYTES);

    quant_kernel<<<QBLK, 256>>>(I, S);
    gemm_kernel<<<dim3(NT, NT, 1), 256, SMEM_BYTES>>>();
    combine_kernel<<<(2 * BB) / 256, 256>>>(out);
}

// round 16
// speedup vs baseline: 1.0402x; 1.0402x over previous
#include <cuda_runtime.h>
#include <cuda_bf16.h>
#include <cstdint>

// Problem constants
static constexpr int BB  = 8192;   // batch
static constexpr int DK  = 1024;   // embedding dim
static constexpr int NT  = 64;     // 8192 / 128 tiles per side
static constexpr int NCH = 8;      // 1024 / 128 K-chunks (int8: BK=128)
static constexpr float HNW_SCALE = 1.5f;   // 1 + hard_negative_weight

static constexpr int STAGE_BYTES = 32768;            // A(16K) + B(16K) int8
static constexpr int SMEM_BYTES  = 3 * STAGE_BYTES;  // 98304; 2 CTAs/SM

static constexpr int QBLK = 592;   // quant: 4 CTAs/SM, grid-stride 3-4 rows/warp
static constexpr int QWARPS = QBLK * 8;

// ------------------------- device scratch (static, no allocs) -------------------------
__device__ __align__(256) int8_t g_Iq[(size_t)BB * DK];
__device__ __align__(256) int8_t g_Sq[(size_t)BB * DK];
__device__ float g_qsI[BB];        // rowmax/127
__device__ float g_qsS[BB];        // rowmax/127 * 20  (1/T folded here)
__device__ float g_rowMax[NT * BB];
__device__ float g_rowSum[NT * BB];
__device__ float g_rowHn [NT * BB];
__device__ float g_colMax[NT * BB];
__device__ float g_colSum[NT * BB];
__device__ float g_colHn [NT * BB];
__device__ float g_diag  [BB];
__device__ float g_part  [64];
__device__ unsigned g_ctr = 0;

// ------------------------- helpers -------------------------
static __device__ __forceinline__ uint32_t smem_u32(const void* p) {
    uint32_t a;
    asm("{ .reg .u64 t; cvta.to.shared.u64 t, %1; cvt.u32.u64 %0, t; }" : "=r"(a) : "l"(p));
    return a;
}
static __device__ __forceinline__ void cp16(uint32_t s, const void* g) {
    asm volatile("cp.async.cg.shared.global [%0], [%1], 16;" :: "r"(s), "l"(g) : "memory");
}
// Swizzled smem addr for a [128 rows][128 B] tile; 16B chunks xor'd by row&7
static __device__ __forceinline__ uint32_t sw_addr(uint32_t base, int row, int kchunk) {
    return base + (uint32_t)(row * 128) + (uint32_t)(((kchunk ^ (row & 7)) << 4));
}
static __device__ __forceinline__ void ldsm_x4(uint32_t& r0, uint32_t& r1, uint32_t& r2,
                                               uint32_t& r3, uint32_t addr) {
    asm volatile("ldmatrix.sync.aligned.m8n8.x4.shared.b16 {%0,%1,%2,%3}, [%4];"
                 : "=r"(r0), "=r"(r1), "=r"(r2), "=r"(r3) : "r"(addr));
}
static __device__ __forceinline__ void imma16832(int& c0, int& c1, int& c2, int& c3,
                                                 uint32_t a0, uint32_t a1, uint32_t a2,
                                                 uint32_t a3, uint32_t b0, uint32_t b1) {
    asm volatile(
        "mma.sync.aligned.m16n8k32.row.col.s32.s8.s8.s32 "
        "{%0,%1,%2,%3}, {%4,%5,%6,%7}, {%8,%9}, {%0,%1,%2,%3};"
        : "+r"(c0), "+r"(c1), "+r"(c2), "+r"(c3)
        : "r"(a0), "r"(a1), "r"(a2), "r"(a3), "r"(b0), "r"(b1));
}

// ------------------------- kernel 1: fp32 -> int8 quant (persistent warps) ---------------
__global__ void __launch_bounds__(256) quant_kernel(const float* __restrict__ I,
                                                    const float* __restrict__ S) {
    const int gwarp = (blockIdx.x * 256 + threadIdx.x) >> 5;
    const int lane = threadIdx.x & 31;

    for (int w = gwarp; w < 2 * BB; w += QWARPS) {
        const bool isI = w < BB;
        const int r = isI ? w : w - BB;
        const float4* src = (const float4*)((isI ? I : S) + (size_t)r * DK);

        float4 v[8];
        float m = 0.f;
#pragma unroll
        for (int i = 0; i < 8; i++) {
            v[i] = src[lane + 32 * i];
            m = fmaxf(m, fmaxf(fmaxf(fabsf(v[i].x), fabsf(v[i].y)),
                               fmaxf(fabsf(v[i].z), fabsf(v[i].w))));
        }
#pragma unroll
        for (int o = 16; o; o >>= 1) m = fmaxf(m, __shfl_xor_sync(~0u, m, o));
        m = fmaxf(m, 1e-20f);
        const float inv = 127.0f / m;

        char4* dst = (char4*)((isI ? g_Iq : g_Sq) + (size_t)r * DK);
#pragma unroll
        for (int i = 0; i < 8; i++) {
            char4 q;
            q.x = (char)__float2int_rn(v[i].x * inv);
            q.y = (char)__float2int_rn(v[i].y * inv);
            q.z = (char)__float2int_rn(v[i].z * inv);
            q.w = (char)__float2int_rn(v[i].w * inv);
            dst[lane + 32 * i] = q;
        }
        if (lane == 0) {
            if (isI) g_qsI[r] = m / 127.0f;
            else     g_qsS[r] = (m / 127.0f) * 20.0f;
        }
    }
}

// ------------------------- kernel 2: int8 GEMM tile + register epilogue ------------------
static __device__ __forceinline__ void load_chunk(int tid, const int8_t* Ap,
                                                  const int8_t* Bp,
                                                  uint32_t DATA, int kc) {
    int s = kc % 3;
    uint32_t abase = DATA + (uint32_t)s * STAGE_BYTES;
    uint32_t bbase = abase + 16384u;
    const int8_t* ga0 = Ap + kc * 128;
    const int8_t* gb0 = Bp + kc * 128;
#pragma unroll
    for (int i = 0; i < 4; i++) {
        int v = tid + i * 256;
        int row = v >> 3, cv = v & 7;
        cp16(sw_addr(abase, row, cv), ga0 + (size_t)row * DK + cv * 16);
        cp16(sw_addr(bbase, row, cv), gb0 + (size_t)row * DK + cv * 16);
    }
}

__global__ void __launch_bounds__(256, 2) gemm_kernel() {
    extern __shared__ char smem[];
    const uint32_t DATA = smem_u32(smem);
    const int tid = threadIdx.x, wid = tid >> 5, lane = tid & 31;
    const int wm = wid >> 1, wn = wid & 1;   // 4 x 2 warp grid
    const int bx = blockIdx.x, by = blockIdx.y;

    const int8_t* Ap = g_Iq + (size_t)by * 128 * DK;
    const int8_t* Bp = g_Sq + (size_t)bx * 128 * DK;

    int acc[2][8][4];
#pragma unroll
    for (int mt = 0; mt < 2; mt++)
#pragma unroll
        for (int nt = 0; nt < 8; nt++)
#pragma unroll
            for (int q = 0; q < 4; q++) acc[mt][nt][q] = 0;

    load_chunk(tid, Ap, Bp, DATA, 0);
    asm volatile("cp.async.commit_group;" ::: "memory");
    load_chunk(tid, Ap, Bp, DATA, 1);
    asm volatile("cp.async.commit_group;" ::: "memory");

    // ONE barrier per chunk: prefetch k+2 targets the slot consumed in iter k-1.
    for (int k = 0; k < NCH; k++) {
        asm volatile("cp.async.wait_group 1;" ::: "memory");   // stage k arrived
        __syncthreads();
        if (k + 2 < NCH) load_chunk(tid, Ap, Bp, DATA, k + 2);
        asm volatile("cp.async.commit_group;" ::: "memory");   // uniform accounting
        int s = k % 3;
        uint32_t abase = DATA + (uint32_t)s * STAGE_BYTES;
        uint32_t bbase = abase + 16384u;
#pragma unroll
        for (int kk = 0; kk < 4; kk++) {   // 4 x K=32 per 128B chunk-row
            uint32_t a[2][4];
#pragma unroll
            for (int mt = 0; mt < 2; mt++) {
                int row = wm * 32 + mt * 16 + (lane & 15);
                int kch = 2 * kk + (lane >> 4);
                ldsm_x4(a[mt][0], a[mt][1], a[mt][2], a[mt][3], sw_addr(abase, row, kch));
            }
            uint32_t b[8][2];
#pragma unroll
            for (int np = 0; np < 4; np++) {
                int nrow = wn * 64 + np * 16 + (lane & 7) + ((lane >> 4) << 3);
                int kch = 2 * kk + ((lane >> 3) & 1);
                uint32_t r0, r1, r2, r3;
                ldsm_x4(r0, r1, r2, r3, sw_addr(bbase, nrow, kch));
                b[2 * np][0] = r0; b[2 * np][1] = r1;
                b[2 * np + 1][0] = r2; b[2 * np + 1][1] = r3;
            }
#pragma unroll
            for (int mt = 0; mt < 2; mt++)
#pragma unroll
                for (int nt = 0; nt < 8; nt++)
                    imma16832(acc[mt][nt][0], acc[mt][nt][1], acc[mt][nt][2], acc[mt][nt][3],
                              a[mt][0], a[mt][1], a[mt][2], a[mt][3], b[nt][0], b[nt][1]);
        }
    }
    asm volatile("cp.async.wait_group 0;" ::: "memory");
    __syncthreads();   // pipeline smem free -> reuse for tiny epilogue partials

    // ---------------- register epilogue ----------------
    const int rbase = wm * 32 + (lane >> 2);
    const int cbase = wn * 64 + 2 * (lane & 3);
    const bool dT = (bx == by);

    float x[2][8][4];
    {
        float sI[2][2], sS[8][2];
#pragma unroll
        for (int mt = 0; mt < 2; mt++) {
            sI[mt][0] = g_qsI[by * 128 + rbase + mt * 16];
            sI[mt][1] = g_qsI[by * 128 + rbase + mt * 16 + 8];
        }
#pragma unroll
        for (int nt = 0; nt < 8; nt++) {
            sS[nt][0] = g_qsS[bx * 128 + cbase + nt * 8];
            sS[nt][1] = g_qsS[bx * 128 + cbase + nt * 8 + 1];
        }
#pragma unroll
        for (int mt = 0; mt < 2; mt++)
#pragma unroll
            for (int nt = 0; nt < 8; nt++)
#pragma unroll
                for (int qr = 0; qr < 2; qr++)
#pragma unroll
                    for (int qc = 0; qc < 2; qc++)
                        x[mt][nt][qr * 2 + qc] =
                            (float)acc[mt][nt][qr * 2 + qc] * (sI[mt][qr] * sS[nt][qc]);
    }

    float* sm = (float*)smem;
    float* rm = sm;          // [2][128]
    float* rh = sm + 256;    // [2][128]
    float* rs = sm + 512;    // [2][128]
    float* cm = sm + 768;    // [4][128]
    float* ch = sm + 1280;   // [4][128]
    float* cs = sm + 1792;   // [4][128]

    // pass A: maxes (+diag capture)
#pragma unroll
    for (int g = 0; g < 4; g++) {
        int mt = g >> 1, qr = g & 1;
        int r_loc = rbase + mt * 16 + qr * 8;
        float m = -3.4e38f, h = -3.4e38f;
#pragma unroll
        for (int nt = 0; nt < 8; nt++) {
#pragma unroll
            for (int qc = 0; qc < 2; qc++) {
                float v = x[mt][nt][qr * 2 + qc];
                m = fmaxf(m, v);
                int c_loc = cbase + nt * 8 + qc;
                if (dT && c_loc == r_loc) g_diag[by * 128 + r_loc] = v;
                else h = fmaxf(h, v);
            }
        }
        m = fmaxf(m, __shfl_xor_sync(~0u, m, 1));
        m = fmaxf(m, __shfl_xor_sync(~0u, m, 2));
        h = fmaxf(h, __shfl_xor_sync(~0u, h, 1));
        h = fmaxf(h, __shfl_xor_sync(~0u, h, 2));
        if ((lane & 3) == 0) { rm[wn * 128 + r_loc] = m; rh[wn * 128 + r_loc] = h; }
    }
#pragma unroll
    for (int nt = 0; nt < 8; nt++) {
#pragma unroll
        for (int qc = 0; qc < 2; qc++) {
            int c_loc = cbase + nt * 8 + qc;
            float m = -3.4e38f, h = -3.4e38f;
#pragma unroll
            for (int g = 0; g < 4; g++) {
                int mt = g >> 1, qr = g & 1;
                float v = x[mt][nt][qr * 2 + qc];
                m = fmaxf(m, v);
                int r_loc = rbase + mt * 16 + qr * 8;
                if (!(dT && c_loc == r_loc)) h = fmaxf(h, v);
            }
            m = fmaxf(m, __shfl_xor_sync(~0u, m, 4));
            m = fmaxf(m, __shfl_xor_sync(~0u, m, 8));
            m = fmaxf(m, __shfl_xor_sync(~0u, m, 16));
            h = fmaxf(h, __shfl_xor_sync(~0u, h, 4));
            h = fmaxf(h, __shfl_xor_sync(~0u, h, 8));
            h = fmaxf(h, __shfl_xor_sync(~0u, h, 16));
            if ((lane >> 2) == 0) { cm[wm * 128 + c_loc] = m; ch[wm * 128 + c_loc] = h; }
        }
    }
    __syncthreads();

    // pass B: exp sums against the COMBINED maxes (partials then add exactly)
#pragma unroll
    for (int g = 0; g < 4; g++) {
        int mt = g >> 1, qr = g & 1;
        int r_loc = rbase + mt * 16 + qr * 8;
        float mrow = fmaxf(rm[r_loc], rm[128 + r_loc]);
        float s = 0.f;
#pragma unroll
        for (int nt = 0; nt < 8; nt++) {
            s += __expf(x[mt][nt][qr * 2] - mrow);
            s += __expf(x[mt][nt][qr * 2 + 1] - mrow);
        }
        s += __shfl_xor_sync(~0u, s, 1);
        s += __shfl_xor_sync(~0u, s, 2);
        if ((lane & 3) == 0) rs[wn * 128 + r_loc] = s;
    }
#pragma unroll
    for (int nt = 0; nt < 8; nt++) {
#pragma unroll
        for (int qc = 0; qc < 2; qc++) {
            int c_loc = cbase + nt * 8 + qc;
            float mcol = fmaxf(fmaxf(cm[c_loc], cm[128 + c_loc]),
                               fmaxf(cm[256 + c_loc], cm[384 + c_loc]));
            float s = 0.f;
#pragma unroll
            for (int g = 0; g < 4; g++) {
                int mt = g >> 1, qr = g & 1;
                s += __expf(x[mt][nt][qr * 2 + qc] - mcol);
            }
            s += __shfl_xor_sync(~0u, s, 4);
            s += __shfl_xor_sync(~0u, s, 8);
            s += __shfl_xor_sync(~0u, s, 16);
            if ((lane >> 2) == 0) cs[wm * 128 + c_loc] = s;
        }
    }
    __syncthreads();

    // final writes (coalesced: [tile * BB + idx])
    if (tid < 128) {
        int r = tid;
        float m = fmaxf(rm[r], rm[128 + r]);
        float h = fmaxf(rh[r], rh[128 + r]);
        float s = rs[r] + rs[128 + r];
        int rg = by * 128 + r;
        g_rowMax[bx * BB + rg] = m;
        g_rowSum[bx * BB + rg] = s;
        g_rowHn [bx * BB + rg] = h;
    } else {
        int c = tid - 128;
        float m = fmaxf(fmaxf(cm[c], cm[128 + c]), fmaxf(cm[256 + c], cm[384 + c]));
        float h = fmaxf(fmaxf(ch[c], ch[128 + c]), fmaxf(ch[256 + c], ch[384 + c]));
        float s = cs[c] + cs[128 + c] + cs[256 + c] + cs[384 + c];
        int cg = bx * 128 + c;
        g_colMax[by * BB + cg] = m;
        g_colSum[by * BB + cg] = s;
        g_colHn [by * BB + cg] = h;
    }
}

// ------------------------- kernel 3: merge partials -> loss; last block finalizes --------
__global__ void combine_kernel(float* __restrict__ out) {
    int i = blockIdx.x * blockDim.x + threadIdx.x;  // 0 .. 2*BB-1
    int idx = i & (BB - 1);
    const float *PM, *PS, *PH;
    if (i < BB) { PM = g_rowMax; PS = g_rowSum; PH = g_rowHn; }
    else        { PM = g_colMax; PS = g_colSum; PH = g_colHn; }

    float m = -3.4e38f, h = -3.4e38f;
#pragma unroll 8
    for (int t = 0; t < NT; t++) {
        m = fmaxf(m, PM[t * BB + idx]);
        h = fmaxf(h, PH[t * BB + idx]);
    }
    float s = 0.f;
#pragma unroll 8
    for (int t = 0; t < NT; t++)
        s += PS[t * BB + idx] * __expf(PM[t * BB + idx] - m);

    float d = g_diag[idx];
    float loss;
    if (h > 0.f) {
        float M = fmaxf(m, HNW_SCALE * h);
        float S = s * __expf(m - M) - __expf(h - M) + __expf(HNW_SCALE * h - M);
        loss = M + __logf(S) - d;
    } else {
        float dd = HNW_SCALE * d;
        float snd = s - __expf(d - m);
        float M = fmaxf(h, dd);
        float S = snd * __expf(m - M) + __expf(dd - M);
        loss = M + __logf(S) - dd;
    }

    __shared__ float red[256];
    __shared__ bool last;
    red[threadIdx.x] = loss;
    __syncthreads();
    for (int o = 128; o > 0; o >>= 1) {
        if (threadIdx.x < (unsigned)o) red[threadIdx.x] += red[threadIdx.x + o];
        __syncthreads();
    }
    if (threadIdx.x == 0) {
        g_part[blockIdx.x] = red[0];
        __threadfence();
        last = (atomicAdd(&g_ctr, 1u) == 63u);
    }
    __syncthreads();
    if (last && threadIdx.x == 0) {
        float t = 0.f;
#pragma unroll
        for (int b = 0; b < 64; b++) t += g_part[b];
        out[0] = t / (float)(2 * BB);
        g_ctr = 0;  // reset for next graph replay
    }
}

// ------------------------- launch -------------------------
extern "C" void kernel_launch(void* const* d_in, const int* in_sizes, int n_in,
                              void* d_out, int out_size) {
    const float* I = (const float*)d_in[0];
    const float* S = (const float*)d_in[1];
    float* out = (float*)d_out;

    cudaFuncSetAttribute(gemm_kernel, cudaFuncAttributeMaxDynamicSharedMemorySize, SMEM_BYTES);

    quant_kernel<<<QBLK, 256>>>(I, S);
    gemm_kernel<<<dim3(NT, NT, 1), 256, SMEM_BYTES>>>();
    combine_kernel<<<(2 * BB) / 256, 256>>>(out);
}